// round 5
// baseline (speedup 1.0000x reference)
#include <cuda_runtime.h>
#include <cstdint>

#define BSZ 4
#define SEQ 2048
#define DM  512
#define NH  8
#define DKH 64
#define MR  (BSZ * SEQ)   // 8192 flattened rows
#define MWORDS (SEQ / 32) // 64 mask words per row

// Scratch (allocation-free rule: __device__ globals)
__device__ float    g_Qp[(size_t)MR * DM];
__device__ float    g_Kp[(size_t)MR * DM];
__device__ float    g_Vp[(size_t)MR * DM];
__device__ float    g_Y [(size_t)MR * DM];
__device__ uint32_t g_mask[(size_t)BSZ * SEQ * MWORDS];

__device__ __forceinline__ float neg_inf_f() { return __int_as_float(0xff800000u); }

__device__ __forceinline__ uint32_t f2tf(float f) {
    uint32_t u;
    asm("cvt.rna.tf32.f32 %0, %1;" : "=r"(u) : "f"(f));
    return u;
}

__device__ __forceinline__ void mma_tf32(float* c, const uint32_t* a, const uint32_t* b) {
    asm volatile(
        "mma.sync.aligned.m16n8k8.row.col.f32.tf32.tf32.f32 "
        "{%0,%1,%2,%3}, {%4,%5,%6,%7}, {%8,%9}, {%0,%1,%2,%3};\n"
        : "+f"(c[0]), "+f"(c[1]), "+f"(c[2]), "+f"(c[3])
        : "r"(a[0]), "r"(a[1]), "r"(a[2]), "r"(a[3]), "r"(b[0]), "r"(b[1]));
}

__device__ __forceinline__ void ldsm4(uint32_t* r, uint32_t addr) {
    asm volatile("ldmatrix.sync.aligned.m8n8.x4.shared.b16 {%0,%1,%2,%3}, [%4];"
        : "=r"(r[0]), "=r"(r[1]), "=r"(r[2]), "=r"(r[3]) : "r"(addr));
}

__device__ __forceinline__ uint32_t smem_u32(const void* p) {
    return (uint32_t)__cvta_generic_to_shared(p);
}

__device__ __forceinline__ void cp16(uint32_t dst, const void* src) {
    asm volatile("cp.async.cg.shared.global [%0], [%1], 16;\n"
        :: "r"(dst), "l"(src) : "memory");
}
__device__ __forceinline__ void cp_commit() {
    asm volatile("cp.async.commit_group;\n" ::: "memory");
}
__device__ __forceinline__ void cp_wait0() {
    asm volatile("cp.async.wait_group 0;\n" ::: "memory");
}

// ---------------------------------------------------------------------------
// Pack att_mas (0.0/1.0 floats) into bits.
// ---------------------------------------------------------------------------
__global__ __launch_bounds__(256) void pack_mask(const float* __restrict__ am)
{
    const size_t idx = (size_t)blockIdx.x * 256 + threadIdx.x;
    const float v = am[idx];
    const unsigned bal = __ballot_sync(0xffffffffu, v != 0.0f);
    if ((threadIdx.x & 31) == 0) g_mask[idx >> 5] = bal;
}

// ---------------------------------------------------------------------------
// TF32 masked GEMM with cp.async double-buffered k-tiles.
// Y[r][c] = rowmask[r]*sum_k X[r][k]W[c][k]; optionally tf32-round the output.
// Block 128x128x32, 8 warps (2x4), warp tile 64x32. Smem raw floats, pitch 36.
// ---------------------------------------------------------------------------
__global__ __launch_bounds__(256, 2) void gemm_tf32_rowmask(
    const float* __restrict__ X, const float* __restrict__ W,
    const float* __restrict__ rmask, float* __restrict__ Y, int round_out)
{
    extern __shared__ float gsm[];
    float* Xs = gsm;                 // [2][128*36]
    float* Ws = gsm + 2 * 128 * 36;  // [2][128*36]

    const int tid  = threadIdx.x;
    const int lane = tid & 31;
    const int wid  = tid >> 5;
    const int g    = lane >> 2;
    const int tg   = lane & 3;
    const int wm   = wid >> 2;
    const int wn   = wid & 3;
    const int row0 = blockIdx.y << 7;
    const int col0 = blockIdx.x << 7;

    const int lr = tid >> 3;          // 0..31 within 4-step t loop -> rows 0..127
    const int lc = (tid & 7) << 2;    // 0,4,..,28

    float c[4][4][4];
#pragma unroll
    for (int mi = 0; mi < 4; mi++)
#pragma unroll
        for (int nj = 0; nj < 4; nj++)
#pragma unroll
            for (int q = 0; q < 4; q++) c[mi][nj][q] = 0.0f;

    // prologue: issue k-tile 0
#pragma unroll
    for (int t = 0; t < 4; t++) {
        const int r = lr + (t << 5);
        cp16(smem_u32(&Xs[r * 36 + lc]), X + (size_t)(row0 + r) * DM + lc);
        cp16(smem_u32(&Ws[r * 36 + lc]), W + (size_t)(col0 + r) * DM + lc);
    }
    cp_commit();

    for (int kt = 0; kt < 16; kt++) {
        const int cur = kt & 1;
        cp_wait0();
        __syncthreads();
        if (kt + 1 < 16) {
            const int nb = cur ^ 1;
            const int k0 = (kt + 1) << 5;
#pragma unroll
            for (int t = 0; t < 4; t++) {
                const int r = lr + (t << 5);
                cp16(smem_u32(&Xs[nb * 128 * 36 + r * 36 + lc]),
                     X + (size_t)(row0 + r) * DM + k0 + lc);
                cp16(smem_u32(&Ws[nb * 128 * 36 + r * 36 + lc]),
                     W + (size_t)(col0 + r) * DM + k0 + lc);
            }
            cp_commit();
        }

        const float* Xb = Xs + cur * 128 * 36;
        const float* Wb = Ws + cur * 128 * 36;
#pragma unroll
        for (int kk = 0; kk < 4; kk++) {
            uint32_t a[4][4], b[4][2];
            const int kb = kk << 3;
#pragma unroll
            for (int mi = 0; mi < 4; mi++) {
                const int rb = (wm << 6) + (mi << 4);
                a[mi][0] = f2tf(Xb[(rb + g    ) * 36 + kb + tg]);
                a[mi][1] = f2tf(Xb[(rb + g + 8) * 36 + kb + tg]);
                a[mi][2] = f2tf(Xb[(rb + g    ) * 36 + kb + tg + 4]);
                a[mi][3] = f2tf(Xb[(rb + g + 8) * 36 + kb + tg + 4]);
            }
#pragma unroll
            for (int nj = 0; nj < 4; nj++) {
                const int cb = (wn << 5) + (nj << 3);
                b[nj][0] = f2tf(Wb[(cb + g) * 36 + kb + tg]);
                b[nj][1] = f2tf(Wb[(cb + g) * 36 + kb + tg + 4]);
            }
#pragma unroll
            for (int mi = 0; mi < 4; mi++)
#pragma unroll
                for (int nj = 0; nj < 4; nj++) mma_tf32(c[mi][nj], a[mi], b[nj]);
        }
        __syncthreads();
    }

#pragma unroll
    for (int mi = 0; mi < 4; mi++) {
        const int r1 = row0 + (wm << 6) + (mi << 4) + g;
        const int r2 = r1 + 8;
        const float m1 = rmask[r1];
        const float m2 = rmask[r2];
#pragma unroll
        for (int nj = 0; nj < 4; nj++) {
            const int cc = col0 + (wn << 5) + (nj << 3) + (tg << 1);
            float v[4];
            v[0] = m1 * c[mi][nj][0]; v[1] = m1 * c[mi][nj][1];
            v[2] = m2 * c[mi][nj][2]; v[3] = m2 * c[mi][nj][3];
            if (round_out) {
#pragma unroll
                for (int q = 0; q < 4; q++) v[q] = __uint_as_float(f2tf(v[q]));
            }
            float2 v1; v1.x = v[0]; v1.y = v[1];
            float2 v2; v2.x = v[2]; v2.y = v[3];
            *(float2*)(Y + (size_t)r1 * DM + cc) = v1;
            *(float2*)(Y + (size_t)r2 * DM + cc) = v2;
        }
    }
}

// ---------------------------------------------------------------------------
// TF32 flash attention. cp.async double-buffered K/V (raw tf32-rounded bits),
// LDSM fragments for Q/K, shuffle-repacked P (no P smem), scalar V B-frags.
// Smem: Qs[128][68] + Ks[2][64][68] + Vs[2][64][68] = 104448 B -> 2 CTAs/SM.
// ---------------------------------------------------------------------------
__global__ __launch_bounds__(256, 2) void attn_tf32(const float* __restrict__ k_mas)
{
    extern __shared__ float smf[];
    float* Qs = smf;                  // [128][68]
    float* Ks = smf + 128 * 68;       // [2][64][68]
    float* Vs = smf + 128 * 68 + 2 * 64 * 68;  // [2][64][68]

    const int tid  = threadIdx.x;
    const int lane = tid & 31;
    const int wid  = tid >> 5;
    const int g    = lane >> 2;
    const int tg   = lane & 3;
    const int q0   = blockIdx.x << 7;
    const int h    = blockIdx.y;
    const int b    = blockIdx.z;
    const int qrow = wid << 4;

    const float NEGINF = neg_inf_f();

    // LDSM per-lane addresses
    const uint32_t qsA = smem_u32(Qs) + (((qrow + (lane & 15)) * 68 + ((lane >> 4) << 2)) << 2);
    const uint32_t ksB0 = smem_u32(Ks) +
        (((((lane & 7) + ((lane & 16) >> 1)) * 68) + ((lane & 8) >> 1)) << 2);

    // loader mapping (16B per cp.async)
    const int lr = tid >> 4;          // 0..15 per 256-thread step
    const int lc = (tid & 15) << 2;   // 0..60

    // prologue: Q tile + K/V tile 0
    {
        const float* Qb = g_Qp + ((size_t)b * SEQ + q0) * DM + h * DKH;
#pragma unroll
        for (int t = 0; t < 8; t++) {
            const int r = lr + (t << 4);
            cp16(smem_u32(&Qs[r * 68 + lc]), Qb + (size_t)r * DM + lc);
        }
        const float* Kb = g_Kp + ((size_t)b * SEQ) * DM + h * DKH;
        const float* Vb = g_Vp + ((size_t)b * SEQ) * DM + h * DKH;
#pragma unroll
        for (int t = 0; t < 4; t++) {
            const int r = lr + (t << 4);
            cp16(smem_u32(&Ks[r * 68 + lc]), Kb + (size_t)r * DM + lc);
            cp16(smem_u32(&Vs[r * 68 + lc]), Vb + (size_t)r * DM + lc);
        }
        cp_commit();
    }

    float o[8][4];
#pragma unroll
    for (int dj = 0; dj < 8; dj++)
#pragma unroll
        for (int q = 0; q < 4; q++) o[dj][q] = 0.0f;
    float mrow0 = NEGINF, mrow1 = NEGINF, lrow0 = 0.0f, lrow1 = 0.0f;

    const int q1 = q0 + qrow + g;
    const int q2 = q1 + 8;
    const uint32_t* mrow1p = g_mask + ((size_t)b * SEQ + q1) * MWORDS;
    const uint32_t* mrow2p = g_mask + ((size_t)b * SEQ + q2) * MWORDS;

    const int src1 = (lane & ~3) | (tg >> 1);
    const int src2 = src1 + 2;
    const bool oddt = (tg & 1);

    for (int kt = 0; kt < SEQ / 64; kt++) {
        const int cur = kt & 1;
        cp_wait0();
        __syncthreads();   // tile kt visible; all warps done with buffer cur^1

        if (kt + 1 < SEQ / 64) {
            const int nb = cur ^ 1;
            const int kk1 = (kt + 1) << 6;
            const float* Kb = g_Kp + ((size_t)b * SEQ + kk1) * DM + h * DKH;
            const float* Vb = g_Vp + ((size_t)b * SEQ + kk1) * DM + h * DKH;
#pragma unroll
            for (int t = 0; t < 4; t++) {
                const int r = lr + (t << 4);
                cp16(smem_u32(&Ks[(nb * 64 + r) * 68 + lc]), Kb + (size_t)r * DM + lc);
                cp16(smem_u32(&Vs[(nb * 64 + r) * 68 + lc]), Vb + (size_t)r * DM + lc);
            }
            cp_commit();
        }

        // mask words (independent loads, issued early)
        const uint2 mw1 = *(const uint2*)(mrow1p + (kt << 1));
        const uint2 mw2 = *(const uint2*)(mrow2p + (kt << 1));

        // S = Q @ K^T
        float s[8][4];
#pragma unroll
        for (int nj = 0; nj < 8; nj++)
#pragma unroll
            for (int q = 0; q < 4; q++) s[nj][q] = 0.0f;

        const uint32_t ksB = ksB0 + ((cur * 64 * 68) << 2);
#pragma unroll
        for (int kk = 0; kk < 8; kk++) {
            const int kb = kk << 3;
            uint32_t a[4];
            ldsm4(a, qsA + (kb << 2));
#pragma unroll
            for (int njp = 0; njp < 4; njp++) {
                uint32_t bb[4];
                ldsm4(bb, ksB + ((njp * 16 * 68 + kb) << 2));
                mma_tf32(s[2 * njp],     a, bb);
                mma_tf32(s[2 * njp + 1], a, bb + 2);
            }
        }

        // scale + bitmask
#pragma unroll
        for (int nj = 0; nj < 8; nj++) {
            const int j0 = (nj << 3) + (tg << 1);
            const uint32_t w1 = (j0 & 32) ? mw1.y : mw1.x;
            const uint32_t w2 = (j0 & 32) ? mw2.y : mw2.x;
            const int bi = j0 & 31;
            s[nj][0] = ((w1 >> bi) & 1u)       ? s[nj][0] * 0.125f : NEGINF;
            s[nj][1] = ((w1 >> (bi + 1)) & 1u) ? s[nj][1] * 0.125f : NEGINF;
            s[nj][2] = ((w2 >> bi) & 1u)       ? s[nj][2] * 0.125f : NEGINF;
            s[nj][3] = ((w2 >> (bi + 1)) & 1u) ? s[nj][3] * 0.125f : NEGINF;
        }

        // row max across quad
        float rm0 = NEGINF, rm1 = NEGINF;
#pragma unroll
        for (int nj = 0; nj < 8; nj++) {
            rm0 = fmaxf(rm0, fmaxf(s[nj][0], s[nj][1]));
            rm1 = fmaxf(rm1, fmaxf(s[nj][2], s[nj][3]));
        }
        rm0 = fmaxf(rm0, __shfl_xor_sync(0xffffffffu, rm0, 1));
        rm0 = fmaxf(rm0, __shfl_xor_sync(0xffffffffu, rm0, 2));
        rm1 = fmaxf(rm1, __shfl_xor_sync(0xffffffffu, rm1, 1));
        rm1 = fmaxf(rm1, __shfl_xor_sync(0xffffffffu, rm1, 2));

        const float mn0 = fmaxf(mrow0, rm0);
        const float mn1 = fmaxf(mrow1, rm1);
        const float al0 = (mrow0 == mn0) ? 1.0f : __expf(mrow0 - mn0);
        const float al1 = (mrow1 == mn1) ? 1.0f : __expf(mrow1 - mn1);

        float rs0 = 0.0f, rs1 = 0.0f;
#pragma unroll
        for (int nj = 0; nj < 8; nj++) {
            float p0 = (s[nj][0] == NEGINF) ? 0.0f : __expf(s[nj][0] - mn0);
            float p1 = (s[nj][1] == NEGINF) ? 0.0f : __expf(s[nj][1] - mn0);
            float p2 = (s[nj][2] == NEGINF) ? 0.0f : __expf(s[nj][2] - mn1);
            float p3 = (s[nj][3] == NEGINF) ? 0.0f : __expf(s[nj][3] - mn1);
            rs0 += p0 + p1;
            rs1 += p2 + p3;
            // keep tf32-rounded p in registers (bits == rounded float)
            s[nj][0] = __uint_as_float(f2tf(p0));
            s[nj][1] = __uint_as_float(f2tf(p1));
            s[nj][2] = __uint_as_float(f2tf(p2));
            s[nj][3] = __uint_as_float(f2tf(p3));
        }
        rs0 += __shfl_xor_sync(0xffffffffu, rs0, 1);
        rs0 += __shfl_xor_sync(0xffffffffu, rs0, 2);
        rs1 += __shfl_xor_sync(0xffffffffu, rs1, 1);
        rs1 += __shfl_xor_sync(0xffffffffu, rs1, 2);

        lrow0 = lrow0 * al0 + rs0;
        lrow1 = lrow1 * al1 + rs1;
        mrow0 = mn0;
        mrow1 = mn1;

#pragma unroll
        for (int dj = 0; dj < 8; dj++) {
            o[dj][0] *= al0; o[dj][1] *= al0;
            o[dj][2] *= al1; o[dj][3] *= al1;
        }

        // O += P @ V : repack P fragments via quad shuffles (no smem)
        const float* Vb = Vs + cur * 64 * 68;
#pragma unroll
        for (int kk = 0; kk < 8; kk++) {
            const int kb = kk << 3;
            const float v0 = __shfl_sync(0xffffffffu, s[kk][0], src1);
            const float v1 = __shfl_sync(0xffffffffu, s[kk][1], src1);
            const float v2 = __shfl_sync(0xffffffffu, s[kk][2], src1);
            const float v3 = __shfl_sync(0xffffffffu, s[kk][3], src1);
            const float w0 = __shfl_sync(0xffffffffu, s[kk][0], src2);
            const float w1 = __shfl_sync(0xffffffffu, s[kk][1], src2);
            const float w2 = __shfl_sync(0xffffffffu, s[kk][2], src2);
            const float w3 = __shfl_sync(0xffffffffu, s[kk][3], src2);
            uint32_t a[4];
            a[0] = __float_as_uint(oddt ? v1 : v0);
            a[1] = __float_as_uint(oddt ? v3 : v2);
            a[2] = __float_as_uint(oddt ? w1 : w0);
            a[3] = __float_as_uint(oddt ? w3 : w2);
#pragma unroll
            for (int dj = 0; dj < 8; dj++) {
                uint32_t bb[2];
                bb[0] = __float_as_uint(Vb[(kb + tg    ) * 68 + (dj << 3) + g]);
                bb[1] = __float_as_uint(Vb[(kb + tg + 4) * 68 + (dj << 3) + g]);
                mma_tf32(o[dj], a, bb);
            }
        }
    }

    // Epilogue: normalize, post-mask (k_mas indexed by query pos, per reference)
    const float sc0 = k_mas[(size_t)b * SEQ + q1] / lrow0;
    const float sc1 = k_mas[(size_t)b * SEQ + q2] / lrow1;
    float* Y1 = g_Y + ((size_t)b * SEQ + q1) * DM + h * DKH;
    float* Y2 = g_Y + ((size_t)b * SEQ + q2) * DM + h * DKH;
#pragma unroll
    for (int dj = 0; dj < 8; dj++) {
        const int cc = (dj << 3) + (tg << 1);
        float2 v1; v1.x = o[dj][0] * sc0; v1.y = o[dj][1] * sc0;
        float2 v2; v2.x = o[dj][2] * sc1; v2.y = o[dj][3] * sc1;
        *(float2*)(Y1 + cc) = v1;
        *(float2*)(Y2 + cc) = v2;
    }
}

// ---------------------------------------------------------------------------
extern "C" void kernel_launch(void* const* d_in, const int* in_sizes, int n_in,
                              void* d_out, int out_size)
{
    (void)in_sizes; (void)n_in; (void)out_size;
    const float* Q   = (const float*)d_in[0];
    const float* K   = (const float*)d_in[1];
    const float* V   = (const float*)d_in[2];
    const float* qm  = (const float*)d_in[3];
    const float* km  = (const float*)d_in[4];
    const float* am  = (const float*)d_in[5];
    const float* WQ  = (const float*)d_in[6];
    const float* WK  = (const float*)d_in[7];
    const float* WV  = (const float*)d_in[8];
    const float* WO  = (const float*)d_in[9];
    float* out = (float*)d_out;

    float *Qp, *Kp, *Vp, *Y;
    cudaGetSymbolAddress((void**)&Qp, g_Qp);
    cudaGetSymbolAddress((void**)&Kp, g_Kp);
    cudaGetSymbolAddress((void**)&Vp, g_Vp);
    cudaGetSymbolAddress((void**)&Y,  g_Y);

    const dim3 ggrid(DM / 128, MR / 128);
    const int gemm_smem = 2 * 2 * 128 * 36 * (int)sizeof(float);   // 73728
    cudaFuncSetAttribute(gemm_tf32_rowmask,
                         cudaFuncAttributeMaxDynamicSharedMemorySize, gemm_smem);

    pack_mask<<<(BSZ * SEQ * SEQ) / 256, 256>>>(am);
    gemm_tf32_rowmask<<<ggrid, 256, gemm_smem>>>(Q, WQ, qm, Qp, 1);
    gemm_tf32_rowmask<<<ggrid, 256, gemm_smem>>>(K, WK, km, Kp, 1);
    gemm_tf32_rowmask<<<ggrid, 256, gemm_smem>>>(V, WV, km, Vp, 1);

    const int attn_smem = (128 * 68 + 2 * 64 * 68 + 2 * 64 * 68) * (int)sizeof(float); // 104448
    cudaFuncSetAttribute(attn_tf32, cudaFuncAttributeMaxDynamicSharedMemorySize,
                         attn_smem);
    attn_tf32<<<dim3(SEQ / 128, NH, BSZ), 256, attn_smem>>>(km);

    gemm_tf32_rowmask<<<ggrid, 256, gemm_smem>>>(Y, WO, km, out, 0);
}

// round 6
// speedup vs baseline: 1.0752x; 1.0752x over previous
#include <cuda_runtime.h>
#include <cstdint>

#define BSZ 4
#define SEQ 2048
#define DM  512
#define NH  8
#define DKH 64
#define MR  (BSZ * SEQ)   // 8192 flattened rows
#define MWORDS (SEQ / 32) // 64 mask words per row

// Scratch (allocation-free rule: __device__ globals)
__device__ float    g_Qp[(size_t)MR * DM];
__device__ float    g_Kp[(size_t)MR * DM];
__device__ float    g_Vp[(size_t)MR * DM];
__device__ float    g_Y [(size_t)MR * DM];
__device__ uint32_t g_mask[(size_t)BSZ * SEQ * MWORDS];

__device__ __forceinline__ float neg_inf_f() { return __int_as_float(0xff800000u); }

__device__ __forceinline__ uint32_t f2tf(float f) {
    uint32_t u;
    asm("cvt.rna.tf32.f32 %0, %1;" : "=r"(u) : "f"(f));
    return u;
}

__device__ __forceinline__ void mma_tf32(float* c, const uint32_t* a, const uint32_t* b) {
    asm volatile(
        "mma.sync.aligned.m16n8k8.row.col.f32.tf32.tf32.f32 "
        "{%0,%1,%2,%3}, {%4,%5,%6,%7}, {%8,%9}, {%0,%1,%2,%3};\n"
        : "+f"(c[0]), "+f"(c[1]), "+f"(c[2]), "+f"(c[3])
        : "r"(a[0]), "r"(a[1]), "r"(a[2]), "r"(a[3]), "r"(b[0]), "r"(b[1]));
}

__device__ __forceinline__ void ldsm4(uint32_t* r, uint32_t addr) {
    asm volatile("ldmatrix.sync.aligned.m8n8.x4.shared.b16 {%0,%1,%2,%3}, [%4];"
        : "=r"(r[0]), "=r"(r[1]), "=r"(r[2]), "=r"(r[3]) : "r"(addr));
}

__device__ __forceinline__ uint32_t smem_u32(const void* p) {
    return (uint32_t)__cvta_generic_to_shared(p);
}

__device__ __forceinline__ void cp16(uint32_t dst, const void* src) {
    asm volatile("cp.async.cg.shared.global [%0], [%1], 16;\n"
        :: "r"(dst), "l"(src) : "memory");
}
__device__ __forceinline__ void cp_commit() {
    asm volatile("cp.async.commit_group;\n" ::: "memory");
}
__device__ __forceinline__ void cp_wait0() {
    asm volatile("cp.async.wait_group 0;\n" ::: "memory");
}

// ---------------------------------------------------------------------------
// Pack att_mas (0.0/1.0 floats) into bits.
// ---------------------------------------------------------------------------
__global__ __launch_bounds__(256) void pack_mask(const float* __restrict__ am)
{
    const size_t idx = (size_t)blockIdx.x * 256 + threadIdx.x;
    const float v = am[idx];
    const unsigned bal = __ballot_sync(0xffffffffu, v != 0.0f);
    if ((threadIdx.x & 31) == 0) g_mask[idx >> 5] = bal;
}

// ---------------------------------------------------------------------------
// TF32 masked GEMM body (cp.async double-buffered k-tiles).
// Y[r][c] = rowmask[r]*sum_k X[r][k]W[c][k]; optionally tf32-round output.
// Block 128x128x32, 8 warps (2x4), warp tile 64x32.
// ---------------------------------------------------------------------------
__device__ __forceinline__ void gemm_body(
    const float* __restrict__ X, const float* __restrict__ W,
    const float* __restrict__ rmask, float* __restrict__ Y, int round_out,
    int row0, int col0)
{
    extern __shared__ float gsm[];
    float* Xs = gsm;                 // [2][128*36]
    float* Ws = gsm + 2 * 128 * 36;  // [2][128*36]

    const int tid  = threadIdx.x;
    const int lane = tid & 31;
    const int wid  = tid >> 5;
    const int g    = lane >> 2;
    const int tg   = lane & 3;
    const int wm   = wid >> 2;
    const int wn   = wid & 3;

    const int lr = tid >> 3;          // 0..31
    const int lc = (tid & 7) << 2;    // 0,4,..,28

    float c[4][4][4];
#pragma unroll
    for (int mi = 0; mi < 4; mi++)
#pragma unroll
        for (int nj = 0; nj < 4; nj++)
#pragma unroll
            for (int q = 0; q < 4; q++) c[mi][nj][q] = 0.0f;

#pragma unroll
    for (int t = 0; t < 4; t++) {
        const int r = lr + (t << 5);
        cp16(smem_u32(&Xs[r * 36 + lc]), X + (size_t)(row0 + r) * DM + lc);
        cp16(smem_u32(&Ws[r * 36 + lc]), W + (size_t)(col0 + r) * DM + lc);
    }
    cp_commit();

    for (int kt = 0; kt < 16; kt++) {
        const int cur = kt & 1;
        cp_wait0();
        __syncthreads();
        if (kt + 1 < 16) {
            const int nb = cur ^ 1;
            const int k0 = (kt + 1) << 5;
#pragma unroll
            for (int t = 0; t < 4; t++) {
                const int r = lr + (t << 5);
                cp16(smem_u32(&Xs[nb * 128 * 36 + r * 36 + lc]),
                     X + (size_t)(row0 + r) * DM + k0 + lc);
                cp16(smem_u32(&Ws[nb * 128 * 36 + r * 36 + lc]),
                     W + (size_t)(col0 + r) * DM + k0 + lc);
            }
            cp_commit();
        }

        const float* Xb = Xs + cur * 128 * 36;
        const float* Wb = Ws + cur * 128 * 36;
#pragma unroll
        for (int kk = 0; kk < 4; kk++) {
            uint32_t a[4][4], b[4][2];
            const int kb = kk << 3;
#pragma unroll
            for (int mi = 0; mi < 4; mi++) {
                const int rb = (wm << 6) + (mi << 4);
                a[mi][0] = f2tf(Xb[(rb + g    ) * 36 + kb + tg]);
                a[mi][1] = f2tf(Xb[(rb + g + 8) * 36 + kb + tg]);
                a[mi][2] = f2tf(Xb[(rb + g    ) * 36 + kb + tg + 4]);
                a[mi][3] = f2tf(Xb[(rb + g + 8) * 36 + kb + tg + 4]);
            }
#pragma unroll
            for (int nj = 0; nj < 4; nj++) {
                const int cb = (wn << 5) + (nj << 3);
                b[nj][0] = f2tf(Wb[(cb + g) * 36 + kb + tg]);
                b[nj][1] = f2tf(Wb[(cb + g) * 36 + kb + tg + 4]);
            }
#pragma unroll
            for (int mi = 0; mi < 4; mi++)
#pragma unroll
                for (int nj = 0; nj < 4; nj++) mma_tf32(c[mi][nj], a[mi], b[nj]);
        }
        __syncthreads();
    }

#pragma unroll
    for (int mi = 0; mi < 4; mi++) {
        const int r1 = row0 + (wm << 6) + (mi << 4) + g;
        const int r2 = r1 + 8;
        const float m1 = rmask[r1];
        const float m2 = rmask[r2];
#pragma unroll
        for (int nj = 0; nj < 4; nj++) {
            const int cc = col0 + (wn << 5) + (nj << 3) + (tg << 1);
            float v[4];
            v[0] = m1 * c[mi][nj][0]; v[1] = m1 * c[mi][nj][1];
            v[2] = m2 * c[mi][nj][2]; v[3] = m2 * c[mi][nj][3];
            if (round_out) {
#pragma unroll
                for (int q = 0; q < 4; q++) v[q] = __uint_as_float(f2tf(v[q]));
            }
            float2 v1; v1.x = v[0]; v1.y = v[1];
            float2 v2; v2.x = v[2]; v2.y = v[3];
            *(float2*)(Y + (size_t)r1 * DM + cc) = v1;
            *(float2*)(Y + (size_t)r2 * DM + cc) = v2;
        }
    }
}

// Fused Q/K/V projections: blockIdx.z selects (X, W, mask, out) triple.
__global__ __launch_bounds__(256, 2) void gemm_qkv(
    const float* __restrict__ Qin, const float* __restrict__ Kin,
    const float* __restrict__ Vin,
    const float* __restrict__ WQ, const float* __restrict__ WK,
    const float* __restrict__ WV,
    const float* __restrict__ qm, const float* __restrict__ km)
{
    const float* X; const float* W; const float* msk; float* Y;
    if (blockIdx.z == 0)      { X = Qin; W = WQ; msk = qm; Y = g_Qp; }
    else if (blockIdx.z == 1) { X = Kin; W = WK; msk = km; Y = g_Kp; }
    else                      { X = Vin; W = WV; msk = km; Y = g_Vp; }
    gemm_body(X, W, msk, Y, 1, blockIdx.y << 7, blockIdx.x << 7);
}

// Single GEMM (used for WO).
__global__ __launch_bounds__(256, 2) void gemm_single(
    const float* __restrict__ X, const float* __restrict__ W,
    const float* __restrict__ rmask, float* __restrict__ Y, int round_out)
{
    gemm_body(X, W, rmask, Y, round_out, blockIdx.y << 7, blockIdx.x << 7);
}

// ---------------------------------------------------------------------------
// TF32 flash attention. 128 threads = 4 warps x 32 query rows (two m16 tiles).
// K/V fragments reused across both m-tiles (2 MMAs per fragment).
// cp.async double-buffered K/V; LDSM for Q/K; shuffle-repacked P; scalar V.
// Smem: Qs[128][68] + Ks[2][64][68] + Vs[2][64][68] = 104448 B -> 2 CTAs/SM.
// ---------------------------------------------------------------------------
__global__ __launch_bounds__(128, 2) void attn_tf32(const float* __restrict__ k_mas)
{
    extern __shared__ float smf[];
    float* Qs = smf;                  // [128][68]
    float* Ks = smf + 128 * 68;       // [2][64][68]
    float* Vs = smf + 128 * 68 + 2 * 64 * 68;  // [2][64][68]

    const int tid  = threadIdx.x;
    const int lane = tid & 31;
    const int wid  = tid >> 5;        // 0..3
    const int g    = lane >> 2;
    const int tg   = lane & 3;
    const int q0   = blockIdx.x << 7;
    const int h    = blockIdx.y;
    const int b    = blockIdx.z;
    const int qrow = wid << 5;        // warp's first query row (32 rows/warp)

    const float NEGINF = neg_inf_f();

    // LDSM A addresses for the two m16 tiles of this warp
    uint32_t qsA[2];
#pragma unroll
    for (int mi = 0; mi < 2; mi++)
        qsA[mi] = smem_u32(Qs) +
            (((qrow + (mi << 4) + (lane & 15)) * 68 + ((lane >> 4) << 2)) << 2);
    const uint32_t ksB0 = smem_u32(Ks) +
        (((((lane & 7) + ((lane & 16) >> 1)) * 68) + ((lane & 8) >> 1)) << 2);

    // loader mapping (16B per cp.async), 128 threads
    const int lr = tid >> 4;          // 0..7
    const int lc = (tid & 15) << 2;   // 0..60

    // prologue: Q tile (128x64) + K/V tile 0
    {
        const float* Qb = g_Qp + ((size_t)b * SEQ + q0) * DM + h * DKH;
#pragma unroll
        for (int t = 0; t < 16; t++) {
            const int r = lr + (t << 3);
            cp16(smem_u32(&Qs[r * 68 + lc]), Qb + (size_t)r * DM + lc);
        }
        const float* Kb = g_Kp + ((size_t)b * SEQ) * DM + h * DKH;
        const float* Vb = g_Vp + ((size_t)b * SEQ) * DM + h * DKH;
#pragma unroll
        for (int t = 0; t < 8; t++) {
            const int r = lr + (t << 3);
            cp16(smem_u32(&Ks[r * 68 + lc]), Kb + (size_t)r * DM + lc);
            cp16(smem_u32(&Vs[r * 68 + lc]), Vb + (size_t)r * DM + lc);
        }
        cp_commit();
    }

    float o[2][8][4];
#pragma unroll
    for (int mi = 0; mi < 2; mi++)
#pragma unroll
        for (int dj = 0; dj < 8; dj++)
#pragma unroll
            for (int q = 0; q < 4; q++) o[mi][dj][q] = 0.0f;
    float mrow[2][2], lrow[2][2];
#pragma unroll
    for (int mi = 0; mi < 2; mi++) {
        mrow[mi][0] = NEGINF; mrow[mi][1] = NEGINF;
        lrow[mi][0] = 0.0f;   lrow[mi][1] = 0.0f;
    }

    int qr[2][2];
#pragma unroll
    for (int mi = 0; mi < 2; mi++) {
        qr[mi][0] = q0 + qrow + (mi << 4) + g;
        qr[mi][1] = qr[mi][0] + 8;
    }

    const int src1 = (lane & ~3) | (tg >> 1);
    const int src2 = src1 + 2;
    const bool oddt = (tg & 1);

    for (int kt = 0; kt < SEQ / 64; kt++) {
        const int cur = kt & 1;
        cp_wait0();
        __syncthreads();

        if (kt + 1 < SEQ / 64) {
            const int nb = cur ^ 1;
            const int kk1 = (kt + 1) << 6;
            const float* Kb = g_Kp + ((size_t)b * SEQ + kk1) * DM + h * DKH;
            const float* Vb = g_Vp + ((size_t)b * SEQ + kk1) * DM + h * DKH;
#pragma unroll
            for (int t = 0; t < 8; t++) {
                const int r = lr + (t << 3);
                cp16(smem_u32(&Ks[(nb * 64 + r) * 68 + lc]), Kb + (size_t)r * DM + lc);
                cp16(smem_u32(&Vs[(nb * 64 + r) * 68 + lc]), Vb + (size_t)r * DM + lc);
            }
            cp_commit();
        }

        // mask words for 4 rows
        uint2 mw[2][2];
#pragma unroll
        for (int mi = 0; mi < 2; mi++) {
            mw[mi][0] = *(const uint2*)(g_mask + ((size_t)b * SEQ + qr[mi][0]) * MWORDS + (kt << 1));
            mw[mi][1] = *(const uint2*)(g_mask + ((size_t)b * SEQ + qr[mi][1]) * MWORDS + (kt << 1));
        }

        // S = Q @ K^T  (K fragments shared across both m-tiles)
        float s[2][8][4];
#pragma unroll
        for (int mi = 0; mi < 2; mi++)
#pragma unroll
            for (int nj = 0; nj < 8; nj++)
#pragma unroll
                for (int q = 0; q < 4; q++) s[mi][nj][q] = 0.0f;

        const uint32_t ksB = ksB0 + ((cur * 64 * 68) << 2);
#pragma unroll
        for (int kk = 0; kk < 8; kk++) {
            const int kb = kk << 3;
            uint32_t a0[4], a1[4];
            ldsm4(a0, qsA[0] + (kb << 2));
            ldsm4(a1, qsA[1] + (kb << 2));
#pragma unroll
            for (int njp = 0; njp < 4; njp++) {
                uint32_t bb[4];
                ldsm4(bb, ksB + ((njp * 16 * 68 + kb) << 2));
                mma_tf32(s[0][2 * njp],     a0, bb);
                mma_tf32(s[0][2 * njp + 1], a0, bb + 2);
                mma_tf32(s[1][2 * njp],     a1, bb);
                mma_tf32(s[1][2 * njp + 1], a1, bb + 2);
            }
        }

        // scale + bitmask, softmax update per m-tile
#pragma unroll
        for (int mi = 0; mi < 2; mi++) {
#pragma unroll
            for (int nj = 0; nj < 8; nj++) {
                const int j0 = (nj << 3) + (tg << 1);
                const uint32_t w1 = (j0 & 32) ? mw[mi][0].y : mw[mi][0].x;
                const uint32_t w2 = (j0 & 32) ? mw[mi][1].y : mw[mi][1].x;
                const int bi = j0 & 31;
                s[mi][nj][0] = ((w1 >> bi) & 1u)       ? s[mi][nj][0] * 0.125f : NEGINF;
                s[mi][nj][1] = ((w1 >> (bi + 1)) & 1u) ? s[mi][nj][1] * 0.125f : NEGINF;
                s[mi][nj][2] = ((w2 >> bi) & 1u)       ? s[mi][nj][2] * 0.125f : NEGINF;
                s[mi][nj][3] = ((w2 >> (bi + 1)) & 1u) ? s[mi][nj][3] * 0.125f : NEGINF;
            }

            float rm0 = NEGINF, rm1 = NEGINF;
#pragma unroll
            for (int nj = 0; nj < 8; nj++) {
                rm0 = fmaxf(rm0, fmaxf(s[mi][nj][0], s[mi][nj][1]));
                rm1 = fmaxf(rm1, fmaxf(s[mi][nj][2], s[mi][nj][3]));
            }
            rm0 = fmaxf(rm0, __shfl_xor_sync(0xffffffffu, rm0, 1));
            rm0 = fmaxf(rm0, __shfl_xor_sync(0xffffffffu, rm0, 2));
            rm1 = fmaxf(rm1, __shfl_xor_sync(0xffffffffu, rm1, 1));
            rm1 = fmaxf(rm1, __shfl_xor_sync(0xffffffffu, rm1, 2));

            const float mn0 = fmaxf(mrow[mi][0], rm0);
            const float mn1 = fmaxf(mrow[mi][1], rm1);
            const float al0 = (mrow[mi][0] == mn0) ? 1.0f : __expf(mrow[mi][0] - mn0);
            const float al1 = (mrow[mi][1] == mn1) ? 1.0f : __expf(mrow[mi][1] - mn1);

            float rs0 = 0.0f, rs1 = 0.0f;
#pragma unroll
            for (int nj = 0; nj < 8; nj++) {
                float p0 = (s[mi][nj][0] == NEGINF) ? 0.0f : __expf(s[mi][nj][0] - mn0);
                float p1 = (s[mi][nj][1] == NEGINF) ? 0.0f : __expf(s[mi][nj][1] - mn0);
                float p2 = (s[mi][nj][2] == NEGINF) ? 0.0f : __expf(s[mi][nj][2] - mn1);
                float p3 = (s[mi][nj][3] == NEGINF) ? 0.0f : __expf(s[mi][nj][3] - mn1);
                rs0 += p0 + p1;
                rs1 += p2 + p3;
                s[mi][nj][0] = __uint_as_float(f2tf(p0));
                s[mi][nj][1] = __uint_as_float(f2tf(p1));
                s[mi][nj][2] = __uint_as_float(f2tf(p2));
                s[mi][nj][3] = __uint_as_float(f2tf(p3));
            }
            rs0 += __shfl_xor_sync(0xffffffffu, rs0, 1);
            rs0 += __shfl_xor_sync(0xffffffffu, rs0, 2);
            rs1 += __shfl_xor_sync(0xffffffffu, rs1, 1);
            rs1 += __shfl_xor_sync(0xffffffffu, rs1, 2);

            lrow[mi][0] = lrow[mi][0] * al0 + rs0;
            lrow[mi][1] = lrow[mi][1] * al1 + rs1;
            mrow[mi][0] = mn0;
            mrow[mi][1] = mn1;

#pragma unroll
            for (int dj = 0; dj < 8; dj++) {
                o[mi][dj][0] *= al0; o[mi][dj][1] *= al0;
                o[mi][dj][2] *= al1; o[mi][dj][3] *= al1;
            }
        }

        // O += P @ V : V fragments shared across both m-tiles
        const float* Vb = Vs + cur * 64 * 68;
#pragma unroll
        for (int kk = 0; kk < 8; kk++) {
            const int kb = kk << 3;
            uint32_t a[2][4];
#pragma unroll
            for (int mi = 0; mi < 2; mi++) {
                const float v0 = __shfl_sync(0xffffffffu, s[mi][kk][0], src1);
                const float v1 = __shfl_sync(0xffffffffu, s[mi][kk][1], src1);
                const float v2 = __shfl_sync(0xffffffffu, s[mi][kk][2], src1);
                const float v3 = __shfl_sync(0xffffffffu, s[mi][kk][3], src1);
                const float w0 = __shfl_sync(0xffffffffu, s[mi][kk][0], src2);
                const float w1 = __shfl_sync(0xffffffffu, s[mi][kk][1], src2);
                const float w2 = __shfl_sync(0xffffffffu, s[mi][kk][2], src2);
                const float w3 = __shfl_sync(0xffffffffu, s[mi][kk][3], src2);
                a[mi][0] = __float_as_uint(oddt ? v1 : v0);
                a[mi][1] = __float_as_uint(oddt ? v3 : v2);
                a[mi][2] = __float_as_uint(oddt ? w1 : w0);
                a[mi][3] = __float_as_uint(oddt ? w3 : w2);
            }
#pragma unroll
            for (int dj = 0; dj < 8; dj++) {
                uint32_t bb[2];
                bb[0] = __float_as_uint(Vb[(kb + tg    ) * 68 + (dj << 3) + g]);
                bb[1] = __float_as_uint(Vb[(kb + tg + 4) * 68 + (dj << 3) + g]);
                mma_tf32(o[0][dj], a[0], bb);
                mma_tf32(o[1][dj], a[1], bb);
            }
        }
    }

    // Epilogue: normalize, post-mask (k_mas indexed by query pos, per reference)
#pragma unroll
    for (int mi = 0; mi < 2; mi++) {
        const float sc0 = k_mas[(size_t)b * SEQ + qr[mi][0]] / lrow[mi][0];
        const float sc1 = k_mas[(size_t)b * SEQ + qr[mi][1]] / lrow[mi][1];
        float* Y1 = g_Y + ((size_t)b * SEQ + qr[mi][0]) * DM + h * DKH;
        float* Y2 = g_Y + ((size_t)b * SEQ + qr[mi][1]) * DM + h * DKH;
#pragma unroll
        for (int dj = 0; dj < 8; dj++) {
            const int cc = (dj << 3) + (tg << 1);
            float2 v1; v1.x = o[mi][dj][0] * sc0; v1.y = o[mi][dj][1] * sc0;
            float2 v2; v2.x = o[mi][dj][2] * sc1; v2.y = o[mi][dj][3] * sc1;
            *(float2*)(Y1 + cc) = v1;
            *(float2*)(Y2 + cc) = v2;
        }
    }
}

// ---------------------------------------------------------------------------
extern "C" void kernel_launch(void* const* d_in, const int* in_sizes, int n_in,
                              void* d_out, int out_size)
{
    (void)in_sizes; (void)n_in; (void)out_size;
    const float* Q   = (const float*)d_in[0];
    const float* K   = (const float*)d_in[1];
    const float* V   = (const float*)d_in[2];
    const float* qm  = (const float*)d_in[3];
    const float* km  = (const float*)d_in[4];
    const float* am  = (const float*)d_in[5];
    const float* WQ  = (const float*)d_in[6];
    const float* WK  = (const float*)d_in[7];
    const float* WV  = (const float*)d_in[8];
    const float* WO  = (const float*)d_in[9];
    float* out = (float*)d_out;

    float *Y;
    cudaGetSymbolAddress((void**)&Y, g_Y);

    const int gemm_smem = 2 * 2 * 128 * 36 * (int)sizeof(float);   // 73728
    cudaFuncSetAttribute(gemm_qkv,
                         cudaFuncAttributeMaxDynamicSharedMemorySize, gemm_smem);
    cudaFuncSetAttribute(gemm_single,
                         cudaFuncAttributeMaxDynamicSharedMemorySize, gemm_smem);

    pack_mask<<<(BSZ * SEQ * SEQ) / 256, 256>>>(am);

    gemm_qkv<<<dim3(DM / 128, MR / 128, 3), 256, gemm_smem>>>(
        Q, K, V, WQ, WK, WV, qm, km);

    const int attn_smem = (128 * 68 + 2 * 64 * 68 + 2 * 64 * 68) * (int)sizeof(float); // 104448
    cudaFuncSetAttribute(attn_tf32, cudaFuncAttributeMaxDynamicSharedMemorySize,
                         attn_smem);
    attn_tf32<<<dim3(SEQ / 128, NH, BSZ), 128, attn_smem>>>(km);

    gemm_single<<<dim3(DM / 128, MR / 128), 256, gemm_smem>>>(Y, WO, km, out, 0);
}

// round 7
// speedup vs baseline: 1.1949x; 1.1114x over previous
#include <cuda_runtime.h>
#include <cstdint>

#define BSZ 4
#define SEQ 2048
#define DM  512
#define NH  8
#define DKH 64
#define MR  (BSZ * SEQ)   // 8192 flattened rows
#define MWORDS (SEQ / 32) // 64 mask words per row

// Scratch (allocation-free rule: __device__ globals)
__device__ float    g_Qp[(size_t)MR * DM];
__device__ float    g_Kp[(size_t)MR * DM];
__device__ float    g_Vp[(size_t)MR * DM];
__device__ float    g_Y [(size_t)MR * DM];
__device__ uint32_t g_mask[(size_t)BSZ * SEQ * MWORDS];

__device__ __forceinline__ float neg_inf_f() { return __int_as_float(0xff800000u); }

__device__ __forceinline__ uint32_t f2tf(float f) {
    uint32_t u;
    asm("cvt.rna.tf32.f32 %0, %1;" : "=r"(u) : "f"(f));
    return u;
}

__device__ __forceinline__ void mma_tf32(float* c, const uint32_t* a, const uint32_t* b) {
    asm volatile(
        "mma.sync.aligned.m16n8k8.row.col.f32.tf32.tf32.f32 "
        "{%0,%1,%2,%3}, {%4,%5,%6,%7}, {%8,%9}, {%0,%1,%2,%3};\n"
        : "+f"(c[0]), "+f"(c[1]), "+f"(c[2]), "+f"(c[3])
        : "r"(a[0]), "r"(a[1]), "r"(a[2]), "r"(a[3]), "r"(b[0]), "r"(b[1]));
}

__device__ __forceinline__ void ldsm4(uint32_t* r, uint32_t addr) {
    asm volatile("ldmatrix.sync.aligned.m8n8.x4.shared.b16 {%0,%1,%2,%3}, [%4];"
        : "=r"(r[0]), "=r"(r[1]), "=r"(r[2]), "=r"(r[3]) : "r"(addr));
}

__device__ __forceinline__ uint32_t smem_u32(const void* p) {
    return (uint32_t)__cvta_generic_to_shared(p);
}

__device__ __forceinline__ void cp16(uint32_t dst, const void* src) {
    asm volatile("cp.async.cg.shared.global [%0], [%1], 16;\n"
        :: "r"(dst), "l"(src) : "memory");
}
__device__ __forceinline__ void cp_commit() {
    asm volatile("cp.async.commit_group;\n" ::: "memory");
}
__device__ __forceinline__ void cp_wait0() {
    asm volatile("cp.async.wait_group 0;\n" ::: "memory");
}

// ---------------------------------------------------------------------------
// Pack att_mas (0.0/1.0 floats) into bits. Warp handles 128 consecutive
// elements via 4 strided coalesced loads + 4 ballots.
// ---------------------------------------------------------------------------
__global__ __launch_bounds__(256) void pack_mask(const float* __restrict__ am)
{
    const int lane = threadIdx.x & 31;
    const size_t wg = (size_t)blockIdx.x * 8 + (threadIdx.x >> 5); // global warp
    const size_t base = wg * 128;
    const float v0 = am[base + lane];
    const float v1 = am[base + 32 + lane];
    const float v2 = am[base + 64 + lane];
    const float v3 = am[base + 96 + lane];
    const unsigned b0 = __ballot_sync(0xffffffffu, v0 != 0.0f);
    const unsigned b1 = __ballot_sync(0xffffffffu, v1 != 0.0f);
    const unsigned b2 = __ballot_sync(0xffffffffu, v2 != 0.0f);
    const unsigned b3 = __ballot_sync(0xffffffffu, v3 != 0.0f);
    if (lane < 4) {
        unsigned w = (lane == 0) ? b0 : (lane == 1) ? b1 : (lane == 2) ? b2 : b3;
        g_mask[wg * 4 + lane] = w;
    }
}

// ---------------------------------------------------------------------------
// TF32 masked GEMM body. cp.async double-buffered k-tiles, raw floats in smem,
// ldmatrix fragment loads + post-LDSM tf32 convert (bit-identical numerics).
// Block 128x128x32, 8 warps (2x4), warp tile 64x32. Pitch 36 floats (144B).
// ---------------------------------------------------------------------------
__device__ __forceinline__ void gemm_body(
    const float* __restrict__ X, const float* __restrict__ W,
    const float* __restrict__ rmask, float* __restrict__ Y, int round_out,
    int row0, int col0)
{
    extern __shared__ float gsm[];
    float* Xs = gsm;                 // [2][128*36]
    float* Ws = gsm + 2 * 128 * 36;  // [2][128*36]

    const int tid  = threadIdx.x;
    const int lane = tid & 31;
    const int wid  = tid >> 5;
    const int g    = lane >> 2;
    const int tg   = lane & 3;
    const int wm   = wid >> 2;
    const int wn   = wid & 3;

    const int lr = tid >> 3;          // 0..31
    const int lc = (tid & 7) << 2;    // 0,4,..,28

    // LDSM per-lane byte offsets (within a buffer)
    const uint32_t aoff = (((wm << 6) + (lane & 15)) * 36 + ((lane >> 4) << 2)) << 2;
    const uint32_t boff = (((wn << 5) + (lane & 7) + ((lane & 16) >> 1)) * 36
                           + ((lane & 8) >> 1)) << 2;
    const uint32_t xsBase = smem_u32(Xs);
    const uint32_t wsBase = smem_u32(Ws);

    float c[4][4][4];
#pragma unroll
    for (int mi = 0; mi < 4; mi++)
#pragma unroll
        for (int nj = 0; nj < 4; nj++)
#pragma unroll
            for (int q = 0; q < 4; q++) c[mi][nj][q] = 0.0f;

#pragma unroll
    for (int t = 0; t < 4; t++) {
        const int r = lr + (t << 5);
        cp16(smem_u32(&Xs[r * 36 + lc]), X + (size_t)(row0 + r) * DM + lc);
        cp16(smem_u32(&Ws[r * 36 + lc]), W + (size_t)(col0 + r) * DM + lc);
    }
    cp_commit();

    for (int kt = 0; kt < 16; kt++) {
        const int cur = kt & 1;
        cp_wait0();
        __syncthreads();
        if (kt + 1 < 16) {
            const int nb = cur ^ 1;
            const int k0 = (kt + 1) << 5;
#pragma unroll
            for (int t = 0; t < 4; t++) {
                const int r = lr + (t << 5);
                cp16(smem_u32(&Xs[nb * 128 * 36 + r * 36 + lc]),
                     X + (size_t)(row0 + r) * DM + k0 + lc);
                cp16(smem_u32(&Ws[nb * 128 * 36 + r * 36 + lc]),
                     W + (size_t)(col0 + r) * DM + k0 + lc);
            }
            cp_commit();
        }

        const uint32_t xb = xsBase + ((cur * 128 * 36) << 2) + aoff;
        const uint32_t wb = wsBase + ((cur * 128 * 36) << 2) + boff;
#pragma unroll
        for (int kk = 0; kk < 4; kk++) {
            const int kbb = (kk << 3) << 2;   // byte offset of k-section
            uint32_t a[4][4], b[2][4];
#pragma unroll
            for (int mi = 0; mi < 4; mi++) {
                ldsm4(a[mi], xb + mi * (16 * 36 * 4) + kbb);
#pragma unroll
                for (int q = 0; q < 4; q++)
                    a[mi][q] = f2tf(__uint_as_float(a[mi][q]));
            }
#pragma unroll
            for (int njp = 0; njp < 2; njp++) {
                ldsm4(b[njp], wb + njp * (16 * 36 * 4) + kbb);
#pragma unroll
                for (int q = 0; q < 4; q++)
                    b[njp][q] = f2tf(__uint_as_float(b[njp][q]));
            }
#pragma unroll
            for (int mi = 0; mi < 4; mi++) {
                mma_tf32(c[mi][0], a[mi], b[0]);
                mma_tf32(c[mi][1], a[mi], b[0] + 2);
                mma_tf32(c[mi][2], a[mi], b[1]);
                mma_tf32(c[mi][3], a[mi], b[1] + 2);
            }
        }
        __syncthreads();
    }

#pragma unroll
    for (int mi = 0; mi < 4; mi++) {
        const int r1 = row0 + (wm << 6) + (mi << 4) + g;
        const int r2 = r1 + 8;
        const float m1 = rmask[r1];
        const float m2 = rmask[r2];
#pragma unroll
        for (int nj = 0; nj < 4; nj++) {
            const int cc = col0 + (wn << 5) + (nj << 3) + (tg << 1);
            float v[4];
            v[0] = m1 * c[mi][nj][0]; v[1] = m1 * c[mi][nj][1];
            v[2] = m2 * c[mi][nj][2]; v[3] = m2 * c[mi][nj][3];
            if (round_out) {
#pragma unroll
                for (int q = 0; q < 4; q++) v[q] = __uint_as_float(f2tf(v[q]));
            }
            float2 v1; v1.x = v[0]; v1.y = v[1];
            float2 v2; v2.x = v[2]; v2.y = v[3];
            *(float2*)(Y + (size_t)r1 * DM + cc) = v1;
            *(float2*)(Y + (size_t)r2 * DM + cc) = v2;
        }
    }
}

// Fused Q/K/V projections: blockIdx.z selects (X, W, mask, out) triple.
__global__ __launch_bounds__(256, 2) void gemm_qkv(
    const float* __restrict__ Qin, const float* __restrict__ Kin,
    const float* __restrict__ Vin,
    const float* __restrict__ WQ, const float* __restrict__ WK,
    const float* __restrict__ WV,
    const float* __restrict__ qm, const float* __restrict__ km)
{
    const float* X; const float* W; const float* msk; float* Y;
    if (blockIdx.z == 0)      { X = Qin; W = WQ; msk = qm; Y = g_Qp; }
    else if (blockIdx.z == 1) { X = Kin; W = WK; msk = km; Y = g_Kp; }
    else                      { X = Vin; W = WV; msk = km; Y = g_Vp; }
    gemm_body(X, W, msk, Y, 1, blockIdx.y << 7, blockIdx.x << 7);
}

// Single GEMM (used for WO).
__global__ __launch_bounds__(256, 2) void gemm_single(
    const float* __restrict__ X, const float* __restrict__ W,
    const float* __restrict__ rmask, float* __restrict__ Y, int round_out)
{
    gemm_body(X, W, rmask, Y, round_out, blockIdx.y << 7, blockIdx.x << 7);
}

// ---------------------------------------------------------------------------
// TF32 flash attention. 256 threads = 8 warps x 32 query rows (256-query CTA).
// cp.async double-buffered K/V; LDSM for Q/K/P; P staged in smem; scalar V.
// Smem: Qs[256][68] + Ks[2][64][68] + Vs[2][64][68] + Ps[256][76] = 217088 B.
// One CTA per SM.
// ---------------------------------------------------------------------------
__global__ __launch_bounds__(256, 1) void attn_tf32(const float* __restrict__ k_mas)
{
    extern __shared__ float smf[];
    float* Qs = smf;                                   // [256][68]
    float* Ks = smf + 256 * 68;                        // [2][64][68]
    float* Vs = smf + 256 * 68 + 2 * 64 * 68;          // [2][64][68]
    float* Ps = smf + 256 * 68 + 4 * 64 * 68;          // [256][76]

    const int tid  = threadIdx.x;
    const int lane = tid & 31;
    const int wid  = tid >> 5;        // 0..7
    const int g    = lane >> 2;
    const int tg   = lane & 3;
    const int q0   = blockIdx.x << 8;
    const int h    = blockIdx.y;
    const int b    = blockIdx.z;
    const int qrow = wid << 5;        // 32 query rows per warp

    const float NEGINF = neg_inf_f();

    // LDSM per-lane addresses
    uint32_t qsA[2], psA[2];
#pragma unroll
    for (int mi = 0; mi < 2; mi++) {
        qsA[mi] = smem_u32(Qs) +
            (((qrow + (mi << 4) + (lane & 15)) * 68 + ((lane >> 4) << 2)) << 2);
        psA[mi] = smem_u32(Ps) +
            (((qrow + (mi << 4) + (lane & 15)) * 76 + ((lane >> 4) << 2)) << 2);
    }
    const uint32_t ksB0 = smem_u32(Ks) +
        (((((lane & 7) + ((lane & 16) >> 1)) * 68) + ((lane & 8) >> 1)) << 2);

    // loader mapping (16B per cp.async), 256 threads
    const int lr = tid >> 4;          // 0..15
    const int lc = (tid & 15) << 2;   // 0..60

    // prologue: Q tile (256x64) + K/V tile 0
    {
        const float* Qb = g_Qp + ((size_t)b * SEQ + q0) * DM + h * DKH;
#pragma unroll
        for (int t = 0; t < 16; t++) {
            const int r = lr + (t << 4);
            cp16(smem_u32(&Qs[r * 68 + lc]), Qb + (size_t)r * DM + lc);
        }
        const float* Kb = g_Kp + ((size_t)b * SEQ) * DM + h * DKH;
        const float* Vb = g_Vp + ((size_t)b * SEQ) * DM + h * DKH;
#pragma unroll
        for (int t = 0; t < 4; t++) {
            const int r = lr + (t << 4);
            cp16(smem_u32(&Ks[r * 68 + lc]), Kb + (size_t)r * DM + lc);
            cp16(smem_u32(&Vs[r * 68 + lc]), Vb + (size_t)r * DM + lc);
        }
        cp_commit();
    }

    float o[2][8][4];
#pragma unroll
    for (int mi = 0; mi < 2; mi++)
#pragma unroll
        for (int dj = 0; dj < 8; dj++)
#pragma unroll
            for (int q = 0; q < 4; q++) o[mi][dj][q] = 0.0f;
    float mrow[2][2], lrow[2][2];
#pragma unroll
    for (int mi = 0; mi < 2; mi++) {
        mrow[mi][0] = NEGINF; mrow[mi][1] = NEGINF;
        lrow[mi][0] = 0.0f;   lrow[mi][1] = 0.0f;
    }

    int qr[2][2];
#pragma unroll
    for (int mi = 0; mi < 2; mi++) {
        qr[mi][0] = q0 + qrow + (mi << 4) + g;
        qr[mi][1] = qr[mi][0] + 8;
    }

    for (int kt = 0; kt < SEQ / 64; kt++) {
        const int cur = kt & 1;
        cp_wait0();
        __syncthreads();

        if (kt + 1 < SEQ / 64) {
            const int nb = cur ^ 1;
            const int kk1 = (kt + 1) << 6;
            const float* Kb = g_Kp + ((size_t)b * SEQ + kk1) * DM + h * DKH;
            const float* Vb = g_Vp + ((size_t)b * SEQ + kk1) * DM + h * DKH;
#pragma unroll
            for (int t = 0; t < 4; t++) {
                const int r = lr + (t << 4);
                cp16(smem_u32(&Ks[(nb * 64 + r) * 68 + lc]), Kb + (size_t)r * DM + lc);
                cp16(smem_u32(&Vs[(nb * 64 + r) * 68 + lc]), Vb + (size_t)r * DM + lc);
            }
            cp_commit();
        }

        // mask words for this warp's 4 row-groups
        uint2 mw[2][2];
#pragma unroll
        for (int mi = 0; mi < 2; mi++) {
            mw[mi][0] = *(const uint2*)(g_mask + ((size_t)b * SEQ + qr[mi][0]) * MWORDS + (kt << 1));
            mw[mi][1] = *(const uint2*)(g_mask + ((size_t)b * SEQ + qr[mi][1]) * MWORDS + (kt << 1));
        }

        // S = Q @ K^T  (K fragments shared across both m-tiles)
        float s[2][8][4];
#pragma unroll
        for (int mi = 0; mi < 2; mi++)
#pragma unroll
            for (int nj = 0; nj < 8; nj++)
#pragma unroll
                for (int q = 0; q < 4; q++) s[mi][nj][q] = 0.0f;

        const uint32_t ksB = ksB0 + ((cur * 64 * 68) << 2);
#pragma unroll
        for (int kk = 0; kk < 8; kk++) {
            const int kb = kk << 3;
            uint32_t a0[4], a1[4];
            ldsm4(a0, qsA[0] + (kb << 2));
            ldsm4(a1, qsA[1] + (kb << 2));
#pragma unroll
            for (int njp = 0; njp < 4; njp++) {
                uint32_t bb[4];
                ldsm4(bb, ksB + ((njp * 16 * 68 + kb) << 2));
                mma_tf32(s[0][2 * njp],     a0, bb);
                mma_tf32(s[0][2 * njp + 1], a0, bb + 2);
                mma_tf32(s[1][2 * njp],     a1, bb);
                mma_tf32(s[1][2 * njp + 1], a1, bb + 2);
            }
        }

        // scale + bitmask, softmax update per m-tile; P -> smem
#pragma unroll
        for (int mi = 0; mi < 2; mi++) {
#pragma unroll
            for (int nj = 0; nj < 8; nj++) {
                const int j0 = (nj << 3) + (tg << 1);
                const uint32_t w1 = (j0 & 32) ? mw[mi][0].y : mw[mi][0].x;
                const uint32_t w2 = (j0 & 32) ? mw[mi][1].y : mw[mi][1].x;
                const int bi = j0 & 31;
                s[mi][nj][0] = ((w1 >> bi) & 1u)       ? s[mi][nj][0] * 0.125f : NEGINF;
                s[mi][nj][1] = ((w1 >> (bi + 1)) & 1u) ? s[mi][nj][1] * 0.125f : NEGINF;
                s[mi][nj][2] = ((w2 >> bi) & 1u)       ? s[mi][nj][2] * 0.125f : NEGINF;
                s[mi][nj][3] = ((w2 >> (bi + 1)) & 1u) ? s[mi][nj][3] * 0.125f : NEGINF;
            }

            float rm0 = NEGINF, rm1 = NEGINF;
#pragma unroll
            for (int nj = 0; nj < 8; nj++) {
                rm0 = fmaxf(rm0, fmaxf(s[mi][nj][0], s[mi][nj][1]));
                rm1 = fmaxf(rm1, fmaxf(s[mi][nj][2], s[mi][nj][3]));
            }
            rm0 = fmaxf(rm0, __shfl_xor_sync(0xffffffffu, rm0, 1));
            rm0 = fmaxf(rm0, __shfl_xor_sync(0xffffffffu, rm0, 2));
            rm1 = fmaxf(rm1, __shfl_xor_sync(0xffffffffu, rm1, 1));
            rm1 = fmaxf(rm1, __shfl_xor_sync(0xffffffffu, rm1, 2));

            const float mn0 = fmaxf(mrow[mi][0], rm0);
            const float mn1 = fmaxf(mrow[mi][1], rm1);
            const float al0 = (mrow[mi][0] == mn0) ? 1.0f : __expf(mrow[mi][0] - mn0);
            const float al1 = (mrow[mi][1] == mn1) ? 1.0f : __expf(mrow[mi][1] - mn1);
            // -inf-safe subtrahends: exp(-inf - mn_safe) = 0 without a select
            const float mns0 = fmaxf(mn0, -1.0e30f);
            const float mns1 = fmaxf(mn1, -1.0e30f);

            float rs0 = 0.0f, rs1 = 0.0f;
#pragma unroll
            for (int nj = 0; nj < 8; nj++) {
                float p0 = __expf(s[mi][nj][0] - mns0);
                float p1 = __expf(s[mi][nj][1] - mns0);
                float p2 = __expf(s[mi][nj][2] - mns1);
                float p3 = __expf(s[mi][nj][3] - mns1);
                rs0 += p0 + p1;
                rs1 += p2 + p3;
                const int pc = (nj << 3) + (tg << 1);
                uint2 u1; u1.x = f2tf(p0); u1.y = f2tf(p1);
                uint2 u2; u2.x = f2tf(p2); u2.y = f2tf(p3);
                *(uint2*)&Ps[(qrow + (mi << 4) + g    ) * 76 + pc] = u1;
                *(uint2*)&Ps[(qrow + (mi << 4) + 8 + g) * 76 + pc] = u2;
            }
            rs0 += __shfl_xor_sync(0xffffffffu, rs0, 1);
            rs0 += __shfl_xor_sync(0xffffffffu, rs0, 2);
            rs1 += __shfl_xor_sync(0xffffffffu, rs1, 1);
            rs1 += __shfl_xor_sync(0xffffffffu, rs1, 2);

            lrow[mi][0] = lrow[mi][0] * al0 + rs0;
            lrow[mi][1] = lrow[mi][1] * al1 + rs1;
            mrow[mi][0] = mn0;
            mrow[mi][1] = mn1;

#pragma unroll
            for (int dj = 0; dj < 8; dj++) {
                o[mi][dj][0] *= al0; o[mi][dj][1] *= al0;
                o[mi][dj][2] *= al1; o[mi][dj][3] *= al1;
            }
        }
        __syncwarp();   // P stores visible within warp before LDSM A reads

        // O += P @ V : P via LDSM, V fragments shared across both m-tiles
        const float* Vb = Vs + cur * 64 * 68;
#pragma unroll
        for (int kk = 0; kk < 8; kk++) {
            const int kb = kk << 3;
            uint32_t a[2][4];
            ldsm4(a[0], psA[0] + (kb << 2));
            ldsm4(a[1], psA[1] + (kb << 2));
#pragma unroll
            for (int dj = 0; dj < 8; dj++) {
                uint32_t bb[2];
                bb[0] = __float_as_uint(Vb[(kb + tg    ) * 68 + (dj << 3) + g]);
                bb[1] = __float_as_uint(Vb[(kb + tg + 4) * 68 + (dj << 3) + g]);
                mma_tf32(o[0][dj], a[0], bb);
                mma_tf32(o[1][dj], a[1], bb);
            }
        }
    }

    // Epilogue: normalize, post-mask (k_mas indexed by query pos, per reference)
#pragma unroll
    for (int mi = 0; mi < 2; mi++) {
        const float sc0 = k_mas[(size_t)b * SEQ + qr[mi][0]] / lrow[mi][0];
        const float sc1 = k_mas[(size_t)b * SEQ + qr[mi][1]] / lrow[mi][1];
        float* Y1 = g_Y + ((size_t)b * SEQ + qr[mi][0]) * DM + h * DKH;
        float* Y2 = g_Y + ((size_t)b * SEQ + qr[mi][1]) * DM + h * DKH;
#pragma unroll
        for (int dj = 0; dj < 8; dj++) {
            const int cc = (dj << 3) + (tg << 1);
            float2 v1; v1.x = o[mi][dj][0] * sc0; v1.y = o[mi][dj][1] * sc0;
            float2 v2; v2.x = o[mi][dj][2] * sc1; v2.y = o[mi][dj][3] * sc1;
            *(float2*)(Y1 + cc) = v1;
            *(float2*)(Y2 + cc) = v2;
        }
    }
}

// ---------------------------------------------------------------------------
extern "C" void kernel_launch(void* const* d_in, const int* in_sizes, int n_in,
                              void* d_out, int out_size)
{
    (void)in_sizes; (void)n_in; (void)out_size;
    const float* Q   = (const float*)d_in[0];
    const float* K   = (const float*)d_in[1];
    const float* V   = (const float*)d_in[2];
    const float* qm  = (const float*)d_in[3];
    const float* km  = (const float*)d_in[4];
    const float* am  = (const float*)d_in[5];
    const float* WQ  = (const float*)d_in[6];
    const float* WK  = (const float*)d_in[7];
    const float* WV  = (const float*)d_in[8];
    const float* WO  = (const float*)d_in[9];
    float* out = (float*)d_out;

    float *Y;
    cudaGetSymbolAddress((void**)&Y, g_Y);

    const int gemm_smem = 2 * 2 * 128 * 36 * (int)sizeof(float);   // 73728
    cudaFuncSetAttribute(gemm_qkv,
                         cudaFuncAttributeMaxDynamicSharedMemorySize, gemm_smem);
    cudaFuncSetAttribute(gemm_single,
                         cudaFuncAttributeMaxDynamicSharedMemorySize, gemm_smem);

    pack_mask<<<(BSZ * SEQ * SEQ) / 1024, 256>>>(am);

    gemm_qkv<<<dim3(DM / 128, MR / 128, 3), 256, gemm_smem>>>(
        Q, K, V, WQ, WK, WV, qm, km);

    const int attn_smem = (256 * 68 + 2 * 64 * 68 + 2 * 64 * 68 + 256 * 76)
                          * (int)sizeof(float);  // 217088
    cudaFuncSetAttribute(attn_tf32, cudaFuncAttributeMaxDynamicSharedMemorySize,
                         attn_smem);
    attn_tf32<<<dim3(SEQ / 256, NH, BSZ), 256, attn_smem>>>(km);

    gemm_single<<<dim3(DM / 128, MR / 128), 256, gemm_smem>>>(Y, WO, km, out, 0);
}

// round 8
// speedup vs baseline: 1.2345x; 1.0331x over previous
#include <cuda_runtime.h>
#include <cstdint>

#define BSZ 4
#define SEQ 2048
#define DM  512
#define NH  8
#define DKH 64
#define MR  (BSZ * SEQ)   // 8192 flattened rows
#define MWORDS (SEQ / 32) // 64 mask words per row

// Scratch (allocation-free rule: __device__ globals)
__device__ float    g_Qp[(size_t)MR * DM];
__device__ float    g_Kp[(size_t)MR * DM];
__device__ float    g_Vp[(size_t)MR * DM];
__device__ float    g_Y [(size_t)MR * DM];
__device__ float    g_W [(size_t)4 * DM * DM];   // tf32-rounded WQ|WK|WV|WO
__device__ uint32_t g_mask[(size_t)BSZ * SEQ * MWORDS];

__device__ __forceinline__ float neg_inf_f() { return __int_as_float(0xff800000u); }

__device__ __forceinline__ uint32_t f2tf(float f) {
    uint32_t u;
    asm("cvt.rna.tf32.f32 %0, %1;" : "=r"(u) : "f"(f));
    return u;
}

__device__ __forceinline__ void mma_tf32(float* c, const uint32_t* a, const uint32_t* b) {
    asm volatile(
        "mma.sync.aligned.m16n8k8.row.col.f32.tf32.tf32.f32 "
        "{%0,%1,%2,%3}, {%4,%5,%6,%7}, {%8,%9}, {%0,%1,%2,%3};\n"
        : "+f"(c[0]), "+f"(c[1]), "+f"(c[2]), "+f"(c[3])
        : "r"(a[0]), "r"(a[1]), "r"(a[2]), "r"(a[3]), "r"(b[0]), "r"(b[1]));
}

__device__ __forceinline__ void ldsm4(uint32_t* r, uint32_t addr) {
    asm volatile("ldmatrix.sync.aligned.m8n8.x4.shared.b16 {%0,%1,%2,%3}, [%4];"
        : "=r"(r[0]), "=r"(r[1]), "=r"(r[2]), "=r"(r[3]) : "r"(addr));
}

__device__ __forceinline__ uint32_t smem_u32(const void* p) {
    return (uint32_t)__cvta_generic_to_shared(p);
}

__device__ __forceinline__ void cp16(uint32_t dst, const void* src) {
    asm volatile("cp.async.cg.shared.global [%0], [%1], 16;\n"
        :: "r"(dst), "l"(src) : "memory");
}
__device__ __forceinline__ void cp_commit() {
    asm volatile("cp.async.commit_group;\n" ::: "memory");
}
__device__ __forceinline__ void cp_wait0() {
    asm volatile("cp.async.wait_group 0;\n" ::: "memory");
}
__device__ __forceinline__ void cp_wait1() {
    asm volatile("cp.async.wait_group 1;\n" ::: "memory");
}

// ---------------------------------------------------------------------------
// Prologue: tf32-round the four weight matrices into g_W.
// ---------------------------------------------------------------------------
__global__ __launch_bounds__(256) void round_w(
    const float* __restrict__ WQ, const float* __restrict__ WK,
    const float* __restrict__ WV, const float* __restrict__ WO)
{
    const int idx = blockIdx.x * 256 + threadIdx.x;       // float4 index
    const float* src = (blockIdx.y == 0) ? WQ : (blockIdx.y == 1) ? WK
                     : (blockIdx.y == 2) ? WV : WO;
    float4 v = ((const float4*)src)[idx];
    uint4 u;
    u.x = f2tf(v.x); u.y = f2tf(v.y); u.z = f2tf(v.z); u.w = f2tf(v.w);
    ((uint4*)(g_W + (size_t)blockIdx.y * DM * DM))[idx] = u;
}

// ---------------------------------------------------------------------------
// Pack att_mas (0.0/1.0 floats) into bits.
// ---------------------------------------------------------------------------
__global__ __launch_bounds__(256) void pack_mask(const float* __restrict__ am)
{
    const int lane = threadIdx.x & 31;
    const size_t wg = (size_t)blockIdx.x * 8 + (threadIdx.x >> 5);
    const size_t base = wg * 128;
    const float v0 = am[base + lane];
    const float v1 = am[base + 32 + lane];
    const float v2 = am[base + 64 + lane];
    const float v3 = am[base + 96 + lane];
    const unsigned b0 = __ballot_sync(0xffffffffu, v0 != 0.0f);
    const unsigned b1 = __ballot_sync(0xffffffffu, v1 != 0.0f);
    const unsigned b2 = __ballot_sync(0xffffffffu, v2 != 0.0f);
    const unsigned b3 = __ballot_sync(0xffffffffu, v3 != 0.0f);
    if (lane < 4) {
        unsigned w = (lane == 0) ? b0 : (lane == 1) ? b1 : (lane == 2) ? b2 : b3;
        g_mask[wg * 4 + lane] = w;
    }
}

// ---------------------------------------------------------------------------
// TF32 masked GEMM body. W is pre-rounded (no B cvt). CONV_A selects whether
// A fragments need tf32 rounding (raw inputs) or are already rounded.
// Block 128x128x32, 8 warps (2x4), warp tile 64x32. Pitch 36 floats.
// ---------------------------------------------------------------------------
template<bool CONV_A>
__device__ __forceinline__ void gemm_body(
    const float* __restrict__ X, const float* __restrict__ W,
    const float* __restrict__ rmask, float* __restrict__ Y, int round_out,
    int row0, int col0)
{
    extern __shared__ float gsm[];
    float* Xs = gsm;                 // [2][128*36]
    float* Ws = gsm + 2 * 128 * 36;  // [2][128*36]

    const int tid  = threadIdx.x;
    const int lane = tid & 31;
    const int wid  = tid >> 5;
    const int g    = lane >> 2;
    const int tg   = lane & 3;
    const int wm   = wid >> 2;
    const int wn   = wid & 3;

    const int lr = tid >> 3;          // 0..31
    const int lc = (tid & 7) << 2;    // 0,4,..,28

    const uint32_t aoff = (((wm << 6) + (lane & 15)) * 36 + ((lane >> 4) << 2)) << 2;
    const uint32_t boff = (((wn << 5) + (lane & 7) + ((lane & 16) >> 1)) * 36
                           + ((lane & 8) >> 1)) << 2;
    const uint32_t xsBase = smem_u32(Xs);
    const uint32_t wsBase = smem_u32(Ws);

    float c[4][4][4];
#pragma unroll
    for (int mi = 0; mi < 4; mi++)
#pragma unroll
        for (int nj = 0; nj < 4; nj++)
#pragma unroll
            for (int q = 0; q < 4; q++) c[mi][nj][q] = 0.0f;

#pragma unroll
    for (int t = 0; t < 4; t++) {
        const int r = lr + (t << 5);
        cp16(smem_u32(&Xs[r * 36 + lc]), X + (size_t)(row0 + r) * DM + lc);
        cp16(smem_u32(&Ws[r * 36 + lc]), W + (size_t)(col0 + r) * DM + lc);
    }
    cp_commit();

    for (int kt = 0; kt < 16; kt++) {
        const int cur = kt & 1;
        cp_wait0();
        __syncthreads();
        if (kt + 1 < 16) {
            const int nb = cur ^ 1;
            const int k0 = (kt + 1) << 5;
#pragma unroll
            for (int t = 0; t < 4; t++) {
                const int r = lr + (t << 5);
                cp16(smem_u32(&Xs[nb * 128 * 36 + r * 36 + lc]),
                     X + (size_t)(row0 + r) * DM + k0 + lc);
                cp16(smem_u32(&Ws[nb * 128 * 36 + r * 36 + lc]),
                     W + (size_t)(col0 + r) * DM + k0 + lc);
            }
            cp_commit();
        }

        const uint32_t xb = xsBase + ((cur * 128 * 36) << 2) + aoff;
        const uint32_t wb = wsBase + ((cur * 128 * 36) << 2) + boff;
#pragma unroll
        for (int kk = 0; kk < 4; kk++) {
            const int kbb = (kk << 3) << 2;
            uint32_t a[4][4], b[2][4];
#pragma unroll
            for (int mi = 0; mi < 4; mi++) {
                ldsm4(a[mi], xb + mi * (16 * 36 * 4) + kbb);
                if (CONV_A) {
#pragma unroll
                    for (int q = 0; q < 4; q++)
                        a[mi][q] = f2tf(__uint_as_float(a[mi][q]));
                }
            }
#pragma unroll
            for (int njp = 0; njp < 2; njp++)
                ldsm4(b[njp], wb + njp * (16 * 36 * 4) + kbb);
#pragma unroll
            for (int mi = 0; mi < 4; mi++) {
                mma_tf32(c[mi][0], a[mi], b[0]);
                mma_tf32(c[mi][1], a[mi], b[0] + 2);
                mma_tf32(c[mi][2], a[mi], b[1]);
                mma_tf32(c[mi][3], a[mi], b[1] + 2);
            }
        }
        __syncthreads();
    }

#pragma unroll
    for (int mi = 0; mi < 4; mi++) {
        const int r1 = row0 + (wm << 6) + (mi << 4) + g;
        const int r2 = r1 + 8;
        const float m1 = rmask[r1];
        const float m2 = rmask[r2];
#pragma unroll
        for (int nj = 0; nj < 4; nj++) {
            const int cc = col0 + (wn << 5) + (nj << 3) + (tg << 1);
            float v[4];
            v[0] = m1 * c[mi][nj][0]; v[1] = m1 * c[mi][nj][1];
            v[2] = m2 * c[mi][nj][2]; v[3] = m2 * c[mi][nj][3];
            if (round_out) {
#pragma unroll
                for (int q = 0; q < 4; q++) v[q] = __uint_as_float(f2tf(v[q]));
            }
            float2 v1; v1.x = v[0]; v1.y = v[1];
            float2 v2; v2.x = v[2]; v2.y = v[3];
            *(float2*)(Y + (size_t)r1 * DM + cc) = v1;
            *(float2*)(Y + (size_t)r2 * DM + cc) = v2;
        }
    }
}

// Fused Q/K/V projections (raw X -> A cvt needed; W pre-rounded).
__global__ __launch_bounds__(256, 2) void gemm_qkv(
    const float* __restrict__ Qin, const float* __restrict__ Kin,
    const float* __restrict__ Vin,
    const float* __restrict__ qm, const float* __restrict__ km)
{
    const float* X; const float* W; const float* msk; float* Y;
    if (blockIdx.z == 0)      { X = Qin; W = g_W;               msk = qm; Y = g_Qp; }
    else if (blockIdx.z == 1) { X = Kin; W = g_W + DM * DM;     msk = km; Y = g_Kp; }
    else                      { X = Vin; W = g_W + 2 * DM * DM; msk = km; Y = g_Vp; }
    gemm_body<true>(X, W, msk, Y, 1, blockIdx.y << 7, blockIdx.x << 7);
}

// WO projection: X = g_Y (already tf32-rounded by attention), W pre-rounded.
__global__ __launch_bounds__(256, 2) void gemm_out(
    const float* __restrict__ rmask, float* __restrict__ Y)
{
    gemm_body<false>(g_Y, g_W + 3 * DM * DM, rmask, Y, 0,
                     blockIdx.y << 7, blockIdx.x << 7);
}

// ---------------------------------------------------------------------------
// TF32 flash attention. 256 threads = 8 warps x 32 query rows (256-query CTA).
// Q fragments hoisted to registers (kt-invariant). cp.async double-buffered
// K/V; LDSM for K/P; P staged in smem; scalar V B-frags.
// Smem: Qs[256][68] + Ks[2][64][68] + Vs[2][64][68] + Ps[256][76] = 217088 B.
// ---------------------------------------------------------------------------
__global__ __launch_bounds__(256, 1) void attn_tf32(const float* __restrict__ k_mas)
{
    extern __shared__ float smf[];
    float* Qs = smf;                                   // [256][68]
    float* Ks = smf + 256 * 68;                        // [2][64][68]
    float* Vs = smf + 256 * 68 + 2 * 64 * 68;          // [2][64][68]
    float* Ps = smf + 256 * 68 + 4 * 64 * 68;          // [256][76]

    const int tid  = threadIdx.x;
    const int lane = tid & 31;
    const int wid  = tid >> 5;        // 0..7
    const int g    = lane >> 2;
    const int tg   = lane & 3;
    const int q0   = blockIdx.x << 8;
    const int h    = blockIdx.y;
    const int b    = blockIdx.z;
    const int qrow = wid << 5;        // 32 query rows per warp

    const float NEGINF = neg_inf_f();

    // LDSM per-lane addresses
    uint32_t qsA[2], psA[2];
#pragma unroll
    for (int mi = 0; mi < 2; mi++) {
        qsA[mi] = smem_u32(Qs) +
            (((qrow + (mi << 4) + (lane & 15)) * 68 + ((lane >> 4) << 2)) << 2);
        psA[mi] = smem_u32(Ps) +
            (((qrow + (mi << 4) + (lane & 15)) * 76 + ((lane >> 4) << 2)) << 2);
    }
    const uint32_t ksB0 = smem_u32(Ks) +
        (((((lane & 7) + ((lane & 16) >> 1)) * 68) + ((lane & 8) >> 1)) << 2);

    const int lr = tid >> 4;          // 0..15
    const int lc = (tid & 15) << 2;   // 0..60

    // prologue: Q tile (group 0), then K/V tile 0 (group 1)
    {
        const float* Qb = g_Qp + ((size_t)b * SEQ + q0) * DM + h * DKH;
#pragma unroll
        for (int t = 0; t < 16; t++) {
            const int r = lr + (t << 4);
            cp16(smem_u32(&Qs[r * 68 + lc]), Qb + (size_t)r * DM + lc);
        }
        cp_commit();
        const float* Kb = g_Kp + ((size_t)b * SEQ) * DM + h * DKH;
        const float* Vb = g_Vp + ((size_t)b * SEQ) * DM + h * DKH;
#pragma unroll
        for (int t = 0; t < 4; t++) {
            const int r = lr + (t << 4);
            cp16(smem_u32(&Ks[r * 68 + lc]), Kb + (size_t)r * DM + lc);
            cp16(smem_u32(&Vs[r * 68 + lc]), Vb + (size_t)r * DM + lc);
        }
        cp_commit();
    }

    // wait for Q only (K/V group may still be in flight), hoist Q fragments
    cp_wait1();
    __syncthreads();
    uint32_t qf[2][8][4];
#pragma unroll
    for (int mi = 0; mi < 2; mi++)
#pragma unroll
        for (int kk = 0; kk < 8; kk++)
            ldsm4(qf[mi][kk], qsA[mi] + ((kk << 3) << 2));

    float o[2][8][4];
#pragma unroll
    for (int mi = 0; mi < 2; mi++)
#pragma unroll
        for (int dj = 0; dj < 8; dj++)
#pragma unroll
            for (int q = 0; q < 4; q++) o[mi][dj][q] = 0.0f;
    float mrow[2][2], lrow[2][2];
#pragma unroll
    for (int mi = 0; mi < 2; mi++) {
        mrow[mi][0] = NEGINF; mrow[mi][1] = NEGINF;
        lrow[mi][0] = 0.0f;   lrow[mi][1] = 0.0f;
    }

    int qr[2][2];
#pragma unroll
    for (int mi = 0; mi < 2; mi++) {
        qr[mi][0] = q0 + qrow + (mi << 4) + g;
        qr[mi][1] = qr[mi][0] + 8;
    }

    for (int kt = 0; kt < SEQ / 64; kt++) {
        const int cur = kt & 1;
        cp_wait0();
        __syncthreads();

        if (kt + 1 < SEQ / 64) {
            const int nb = cur ^ 1;
            const int kk1 = (kt + 1) << 6;
            const float* Kb = g_Kp + ((size_t)b * SEQ + kk1) * DM + h * DKH;
            const float* Vb = g_Vp + ((size_t)b * SEQ + kk1) * DM + h * DKH;
#pragma unroll
            for (int t = 0; t < 4; t++) {
                const int r = lr + (t << 4);
                cp16(smem_u32(&Ks[(nb * 64 + r) * 68 + lc]), Kb + (size_t)r * DM + lc);
                cp16(smem_u32(&Vs[(nb * 64 + r) * 68 + lc]), Vb + (size_t)r * DM + lc);
            }
            cp_commit();
        }

        uint2 mw[2][2];
#pragma unroll
        for (int mi = 0; mi < 2; mi++) {
            mw[mi][0] = *(const uint2*)(g_mask + ((size_t)b * SEQ + qr[mi][0]) * MWORDS + (kt << 1));
            mw[mi][1] = *(const uint2*)(g_mask + ((size_t)b * SEQ + qr[mi][1]) * MWORDS + (kt << 1));
        }

        // S = Q @ K^T  (Q from registers, K fragments shared across m-tiles)
        float s[2][8][4];
#pragma unroll
        for (int mi = 0; mi < 2; mi++)
#pragma unroll
            for (int nj = 0; nj < 8; nj++)
#pragma unroll
                for (int q = 0; q < 4; q++) s[mi][nj][q] = 0.0f;

        const uint32_t ksB = ksB0 + ((cur * 64 * 68) << 2);
#pragma unroll
        for (int kk = 0; kk < 8; kk++) {
            const int kb = kk << 3;
#pragma unroll
            for (int njp = 0; njp < 4; njp++) {
                uint32_t bb[4];
                ldsm4(bb, ksB + ((njp * 16 * 68 + kb) << 2));
                mma_tf32(s[0][2 * njp],     qf[0][kk], bb);
                mma_tf32(s[0][2 * njp + 1], qf[0][kk], bb + 2);
                mma_tf32(s[1][2 * njp],     qf[1][kk], bb);
                mma_tf32(s[1][2 * njp + 1], qf[1][kk], bb + 2);
            }
        }

        // scale + bitmask, softmax update per m-tile; P -> smem
#pragma unroll
        for (int mi = 0; mi < 2; mi++) {
#pragma unroll
            for (int nj = 0; nj < 8; nj++) {
                const int j0 = (nj << 3) + (tg << 1);
                const uint32_t w1 = (j0 & 32) ? mw[mi][0].y : mw[mi][0].x;
                const uint32_t w2 = (j0 & 32) ? mw[mi][1].y : mw[mi][1].x;
                const int bi = j0 & 31;
                s[mi][nj][0] = ((w1 >> bi) & 1u)       ? s[mi][nj][0] * 0.125f : NEGINF;
                s[mi][nj][1] = ((w1 >> (bi + 1)) & 1u) ? s[mi][nj][1] * 0.125f : NEGINF;
                s[mi][nj][2] = ((w2 >> bi) & 1u)       ? s[mi][nj][2] * 0.125f : NEGINF;
                s[mi][nj][3] = ((w2 >> (bi + 1)) & 1u) ? s[mi][nj][3] * 0.125f : NEGINF;
            }

            float rm0 = NEGINF, rm1 = NEGINF;
#pragma unroll
            for (int nj = 0; nj < 8; nj++) {
                rm0 = fmaxf(rm0, fmaxf(s[mi][nj][0], s[mi][nj][1]));
                rm1 = fmaxf(rm1, fmaxf(s[mi][nj][2], s[mi][nj][3]));
            }
            rm0 = fmaxf(rm0, __shfl_xor_sync(0xffffffffu, rm0, 1));
            rm0 = fmaxf(rm0, __shfl_xor_sync(0xffffffffu, rm0, 2));
            rm1 = fmaxf(rm1, __shfl_xor_sync(0xffffffffu, rm1, 1));
            rm1 = fmaxf(rm1, __shfl_xor_sync(0xffffffffu, rm1, 2));

            const float mn0 = fmaxf(mrow[mi][0], rm0);
            const float mn1 = fmaxf(mrow[mi][1], rm1);
            const float al0 = (mrow[mi][0] == mn0) ? 1.0f : __expf(mrow[mi][0] - mn0);
            const float al1 = (mrow[mi][1] == mn1) ? 1.0f : __expf(mrow[mi][1] - mn1);
            const float mns0 = fmaxf(mn0, -1.0e30f);
            const float mns1 = fmaxf(mn1, -1.0e30f);

            float rs0 = 0.0f, rs1 = 0.0f;
#pragma unroll
            for (int nj = 0; nj < 8; nj++) {
                float p0 = __expf(s[mi][nj][0] - mns0);
                float p1 = __expf(s[mi][nj][1] - mns0);
                float p2 = __expf(s[mi][nj][2] - mns1);
                float p3 = __expf(s[mi][nj][3] - mns1);
                rs0 += p0 + p1;
                rs1 += p2 + p3;
                const int pc = (nj << 3) + (tg << 1);
                uint2 u1; u1.x = f2tf(p0); u1.y = f2tf(p1);
                uint2 u2; u2.x = f2tf(p2); u2.y = f2tf(p3);
                *(uint2*)&Ps[(qrow + (mi << 4) + g    ) * 76 + pc] = u1;
                *(uint2*)&Ps[(qrow + (mi << 4) + 8 + g) * 76 + pc] = u2;
            }
            rs0 += __shfl_xor_sync(0xffffffffu, rs0, 1);
            rs0 += __shfl_xor_sync(0xffffffffu, rs0, 2);
            rs1 += __shfl_xor_sync(0xffffffffu, rs1, 1);
            rs1 += __shfl_xor_sync(0xffffffffu, rs1, 2);

            lrow[mi][0] = lrow[mi][0] * al0 + rs0;
            lrow[mi][1] = lrow[mi][1] * al1 + rs1;
            mrow[mi][0] = mn0;
            mrow[mi][1] = mn1;

#pragma unroll
            for (int dj = 0; dj < 8; dj++) {
                o[mi][dj][0] *= al0; o[mi][dj][1] *= al0;
                o[mi][dj][2] *= al1; o[mi][dj][3] *= al1;
            }
        }
        __syncwarp();   // P stores visible within warp before LDSM A reads

        // O += P @ V : P via LDSM, V fragments shared across both m-tiles
        const float* Vb = Vs + cur * 64 * 68;
#pragma unroll
        for (int kk = 0; kk < 8; kk++) {
            const int kb = kk << 3;
            uint32_t a[2][4];
            ldsm4(a[0], psA[0] + (kb << 2));
            ldsm4(a[1], psA[1] + (kb << 2));
#pragma unroll
            for (int dj = 0; dj < 8; dj++) {
                uint32_t bb[2];
                bb[0] = __float_as_uint(Vb[(kb + tg    ) * 68 + (dj << 3) + g]);
                bb[1] = __float_as_uint(Vb[(kb + tg + 4) * 68 + (dj << 3) + g]);
                mma_tf32(o[0][dj], a[0], bb);
                mma_tf32(o[1][dj], a[1], bb);
            }
        }
    }

    // Epilogue: normalize, post-mask, tf32-round for the WO GEMM (bit-identical
    // to rounding at the WO fragment load, which is now skipped).
#pragma unroll
    for (int mi = 0; mi < 2; mi++) {
        const float sc0 = k_mas[(size_t)b * SEQ + qr[mi][0]] / lrow[mi][0];
        const float sc1 = k_mas[(size_t)b * SEQ + qr[mi][1]] / lrow[mi][1];
        float* Y1 = g_Y + ((size_t)b * SEQ + qr[mi][0]) * DM + h * DKH;
        float* Y2 = g_Y + ((size_t)b * SEQ + qr[mi][1]) * DM + h * DKH;
#pragma unroll
        for (int dj = 0; dj < 8; dj++) {
            const int cc = (dj << 3) + (tg << 1);
            float2 v1, v2;
            v1.x = __uint_as_float(f2tf(o[mi][dj][0] * sc0));
            v1.y = __uint_as_float(f2tf(o[mi][dj][1] * sc0));
            v2.x = __uint_as_float(f2tf(o[mi][dj][2] * sc1));
            v2.y = __uint_as_float(f2tf(o[mi][dj][3] * sc1));
            *(float2*)(Y1 + cc) = v1;
            *(float2*)(Y2 + cc) = v2;
        }
    }
}

// ---------------------------------------------------------------------------
extern "C" void kernel_launch(void* const* d_in, const int* in_sizes, int n_in,
                              void* d_out, int out_size)
{
    (void)in_sizes; (void)n_in; (void)out_size;
    const float* Q   = (const float*)d_in[0];
    const float* K   = (const float*)d_in[1];
    const float* V   = (const float*)d_in[2];
    const float* qm  = (const float*)d_in[3];
    const float* km  = (const float*)d_in[4];
    const float* am  = (const float*)d_in[5];
    const float* WQ  = (const float*)d_in[6];
    const float* WK  = (const float*)d_in[7];
    const float* WV  = (const float*)d_in[8];
    const float* WO  = (const float*)d_in[9];
    float* out = (float*)d_out;

    const int gemm_smem = 2 * 2 * 128 * 36 * (int)sizeof(float);   // 73728
    cudaFuncSetAttribute(gemm_qkv,
                         cudaFuncAttributeMaxDynamicSharedMemorySize, gemm_smem);
    cudaFuncSetAttribute(gemm_out,
                         cudaFuncAttributeMaxDynamicSharedMemorySize, gemm_smem);

    round_w<<<dim3(DM * DM / 4 / 256, 4), 256>>>(WQ, WK, WV, WO);
    pack_mask<<<(BSZ * SEQ * SEQ) / 1024, 256>>>(am);

    gemm_qkv<<<dim3(DM / 128, MR / 128, 3), 256, gemm_smem>>>(Q, K, V, qm, km);

    const int attn_smem = (256 * 68 + 2 * 64 * 68 + 2 * 64 * 68 + 256 * 76)
                          * (int)sizeof(float);  // 217088
    cudaFuncSetAttribute(attn_tf32, cudaFuncAttributeMaxDynamicSharedMemorySize,
                         attn_smem);
    attn_tf32<<<dim3(SEQ / 256, NH, BSZ), 256, attn_smem>>>(km);

    gemm_out<<<dim3(DM / 128, MR / 128), 256, gemm_smem>>>(km, out);
}